// round 16
// baseline (speedup 1.0000x reference)
#include <cuda_runtime.h>
#include <cuda_fp16.h>
#include <cstdint>

// ---------------------------------------------------------------- shapes
#define BATCH 4
#define SEQ   4096
#define DIM   1024
#define MM    (BATCH * SEQ)   // 16384
#define KK    DIM             // 1024
#define NN    (4 * DIM)       // 4096 : interleaved [q k v g] per dim

// GEMM tiling
#define BM 128
#define BN 128
#define BK 64
#define KITERS (KK / BK)      // 16
#define NBM (MM / BM)         // 128  (= 4 batches x 32 chunks)
#define NBN (NN / BN)         // 32

// ---------------------------------------------------------------- scratch
static __device__ __half g_Ah[(size_t)MM * KK];
static __device__ __half g_Wh[(size_t)NN * KK];     // column-permuted: e' = 4d+j
static __device__ float  g_ball[NN];                 // permuted bias
static __device__ float          g_pref[(size_t)NBM * DIM];  // inclusive chunk prefixes
static __device__ unsigned int   g_flag[NBM * NBN];          // publication flags

// ---------------------------------------------------------------- helpers
__device__ __forceinline__ uint32_t smem_u32(const void* p) {
    uint32_t a;
    asm("{ .reg .u64 t; cvta.to.shared.u64 t, %1; cvt.u32.u64 %0, t; }" : "=r"(a) : "l"(p));
    return a;
}

__device__ __forceinline__ void cp_async16(uint32_t smem_addr, const void* gptr) {
    asm volatile("cp.async.cg.shared.global [%0], [%1], 16;"
                 :: "r"(smem_addr), "l"(gptr) : "memory");
}
#define CP_COMMIT() asm volatile("cp.async.commit_group;" ::: "memory")
#define CP_WAIT1()  asm volatile("cp.async.wait_group 1;" ::: "memory")
#define CP_WAIT0()  asm volatile("cp.async.wait_group 0;" ::: "memory")

__device__ __forceinline__ void ldm_x4(uint32_t* r, uint32_t addr) {
    asm volatile("ldmatrix.sync.aligned.m8n8.x4.shared.b16 {%0,%1,%2,%3}, [%4];"
                 : "=r"(r[0]), "=r"(r[1]), "=r"(r[2]), "=r"(r[3]) : "r"(addr));
}

__device__ __forceinline__ void mma16816(float* c, const uint32_t* a, const uint32_t* b) {
    asm volatile(
        "mma.sync.aligned.m16n8k16.row.col.f32.f16.f16.f32 "
        "{%0,%1,%2,%3}, {%4,%5,%6,%7}, {%8,%9}, {%0,%1,%2,%3};"
        : "+f"(c[0]), "+f"(c[1]), "+f"(c[2]), "+f"(c[3])
        : "r"(a[0]), "r"(a[1]), "r"(a[2]), "r"(a[3]), "r"(b[0]), "r"(b[1]));
}

// ---------------------------------------------------------------- merged setup
#define XB (MM * KK / 4 / 256)
__global__ __launch_bounds__(256)
void setup_kernel(const float* __restrict__ x,
                  const float* __restrict__ Wqkv, const float* __restrict__ bqkv,
                  const float* __restrict__ Wg,   const float* __restrict__ bg)
{
    int blk = blockIdx.x;
    int t   = threadIdx.x;
    if (blk < XB) {
        size_t i = (size_t)blk * 256 + t;
        float4 v = ((const float4*)x)[i];
        size_t o = i * 4;
        g_Ah[o + 0] = __float2half_rn(v.x);
        g_Ah[o + 1] = __float2half_rn(v.y);
        g_Ah[o + 2] = __float2half_rn(v.z);
        g_Ah[o + 3] = __float2half_rn(v.w);
    } else if (blk < XB + NN) {
        int ep = blk - XB;
        int d  = ep >> 2;
        int j  = ep & 3;
        const float* src = (j < 3) ? (Wqkv + (size_t)(j * DIM + d) * KK)
                                   : (Wg + (size_t)d * KK);
        float4 v = ((const float4*)src)[t];
        size_t o = (size_t)ep * KK + t * 4;
        g_Wh[o + 0] = __float2half_rn(v.x);
        g_Wh[o + 1] = __float2half_rn(v.y);
        g_Wh[o + 2] = __float2half_rn(v.z);
        g_Wh[o + 3] = __float2half_rn(v.w);
        if (t == 0)
            g_ball[ep] = (j < 3) ? bqkv[j * DIM + d] : bg[d];
    } else {
        int i = (blk - XB - NN) * 256 + t;
        g_flag[i] = 0u;
    }
}

// ---------------------------------------------------------------- GEMM + fused scan
// SMEM mainloop: stage = A(128x64, pad 72) | B(128x64) = 36864 B; 3 stages = 110592.
// Epilogue overlay: C tile [0,64K); compact (qg,kv) pairs @65536 (32KB);
//                   red @98304 (1KB); red2 @99328.
#define TPAD 72
#define TROW (TPAD * 2)                  // 144 B row stride
#define TILE_B (128 * TROW)              // 18432
#define OFF_A 0
#define OFF_B (TILE_B)
#define STAGE_B (2 * TILE_B)             // 36864
#define NSTAGE 3
#define QC_OFF  65536
#define RED_OFF 98304
#define RED2_OFF 99328
#define GEMM_SMEM (NSTAGE * STAGE_B)     // 110592

// Full-tile load (prologue only).
__device__ __forceinline__ void load_tile(uint32_t s_dst, const __half* g_src,
                                          int k0, int tid)
{
#pragma unroll
    for (int it = 0; it < 4; it++) {
        int c   = tid + it * 256;        // [0,1024)
        int row = c >> 3;
        int kc  = c & 7;
        cp_async16(s_dst + (uint32_t)(row * TROW + kc * 16),
                   (const char*)(g_src + (size_t)row * KK + k0) + kc * 16);
    }
}

__global__ __launch_bounds__(256, 2)
void gemm_fused_kernel(float* __restrict__ out)
{
    extern __shared__ char smem[];
    const uint32_t sb = smem_u32(smem);
    const int tid  = threadIdx.x;
    const int wid  = tid >> 5;
    const int lane = tid & 31;
    const int bm   = blockIdx.y;
    const int bn   = blockIdx.x;
    const int wM   = wid & 3;            // 0..3  (M warp, 32 rows)
    const int wN   = wid >> 2;           // 0..1  (N warp, 64 cols)

    const __half* Ah = g_Ah + (size_t)bm * BM * KK;
    const __half* Bh = g_Wh + (size_t)bn * BN * KK;

    float acc[2][8][4];                  // mi x ni x frag (64 regs)
#pragma unroll
    for (int i = 0; i < 2; i++)
#pragma unroll
        for (int j = 0; j < 8; j++)
#pragma unroll
            for (int r = 0; r < 4; r++) acc[i][j][r] = 0.0f;

    // ldmatrix lane addressing (verified R4-R15):
    const int aRow = wM * 32 + (lane & 15);
    const int aCol = (lane >> 4) * 8;
    const int bRowN = wN * 64 + ((lane >> 4) * 8) + (lane & 7);
    const int bColK = ((lane >> 3) & 1) * 8;
    const uint32_t aOff = (uint32_t)(aRow * TROW + aCol * 2);
    const uint32_t bOff = (uint32_t)(bRowN * TROW + bColK * 2);

    // per-thread cp.async quarter addressing
    const int ldRow = tid >> 3;          // row base within quarter 0 [0,32)
    const int ldKc  = (tid & 7) * 16;    // byte offset within 128B row span

    // ---- prologue: stages 0,1
    load_tile(sb + 0 * STAGE_B + OFF_A, Ah, 0, tid);
    load_tile(sb + 0 * STAGE_B + OFF_B, Bh, 0, tid);
    CP_COMMIT();
    load_tile(sb + 1 * STAGE_B + OFF_A, Ah, BK, tid);
    load_tile(sb + 1 * STAGE_B + OFF_B, Bh, BK, tid);
    CP_COMMIT();

    int slot = 0, nslot = 2;
    for (int i = 0; i < KITERS; i++) {
        if (i < KITERS - 1) { CP_WAIT1(); } else { CP_WAIT0(); }
        __syncthreads();                 // stage i resident; compute(i-1) done

        const bool pf = (i + 2 < KITERS);
        const uint32_t nb = sb + (uint32_t)nslot * STAGE_B;
        const int k0 = (i + 2) * BK;

        const uint32_t aBase = sb + (uint32_t)slot * STAGE_B + OFF_A + aOff;
        const uint32_t bBase = sb + (uint32_t)slot * STAGE_B + OFF_B + bOff;

        // ---- software-pipelined window; prefetch spread at 8 points/iter
        uint32_t afq[2][2][4];           // [slice parity][mi][4]
        uint32_t bq[2][4];               // rotating B pair buffer
        ldm_x4(afq[0][0], aBase);
        ldm_x4(afq[0][1], aBase + 16 * TROW);
        ldm_x4(bq[0], bBase);
#pragma unroll
        for (int ks = 0; ks < 4; ks++) {
            const int kc = ks & 1;
            const int row = ldRow + ks * 32;
            const uint32_t so = (uint32_t)(row * TROW + ldKc);
#pragma unroll
            for (int nh = 0; nh < 4; nh++) {
                const int p = nh & 1;
                // spread prefetch: A-quarter at nh=0, B-quarter at nh=2
                if (pf && nh == 0)
                    cp_async16(nb + OFF_A + so,
                               (const char*)(Ah + (size_t)row * KK + k0) + ldKc);
                if (pf && nh == 2)
                    cp_async16(nb + OFF_B + so,
                               (const char*)(Bh + (size_t)row * KK + k0) + ldKc);
                if (nh < 3)
                    ldm_x4(bq[p ^ 1], bBase + (uint32_t)((nh + 1) * 16 * TROW + ks * 32));
                else if (ks < 3)
                    ldm_x4(bq[p ^ 1], bBase + (uint32_t)((ks + 1) * 32));
                if (ks < 3) {
                    if (nh == 1) ldm_x4(afq[kc ^ 1][0], aBase + (uint32_t)((ks + 1) * 32));
                    if (nh == 2) ldm_x4(afq[kc ^ 1][1], aBase + (uint32_t)(16 * TROW + (ks + 1) * 32));
                }
                mma16816(acc[0][2 * nh],     afq[kc][0], &bq[p][0]);
                mma16816(acc[0][2 * nh + 1], afq[kc][0], &bq[p][2]);
                mma16816(acc[1][2 * nh],     afq[kc][1], &bq[p][0]);
                mma16816(acc[1][2 * nh + 1], afq[kc][1], &bq[p][2]);
            }
        }
        if (pf) CP_COMMIT();
        slot  = (slot == NSTAGE - 1) ? 0 : slot + 1;
        nslot = (nslot == NSTAGE - 1) ? 0 : nslot + 1;
    }

    // ---- fused epilogue with decoupled chained scan --------------------
    __syncthreads();                     // all ldmatrix reads done
    float* C = (float*)smem;             // 128 x 128 f32
    const int g   = lane >> 2;
    const int tig = lane & 3;
#pragma unroll
    for (int mi = 0; mi < 2; mi++) {
#pragma unroll
        for (int ni = 0; ni < 8; ni++) {
            int col  = wN * 64 + ni * 8 + tig * 2;
            int row0 = wM * 32 + mi * 16 + g;
            C[row0 * 128 + col]           = acc[mi][ni][0];
            C[row0 * 128 + col + 1]       = acc[mi][ni][1];
            C[(row0 + 8) * 128 + col]     = acc[mi][ni][2];
            C[(row0 + 8) * 128 + col + 1] = acc[mi][ni][3];
        }
    }
    __syncthreads();

    const int dl = tid & 31;             // local dim 0..31
    const int rg = tid >> 5;             // row group 0..7 (16 rows each)
    const int dg = bn * 32 + dl;         // global dim
    float4 bias = ((const float4*)g_ball)[dg];
    float2* Qc  = (float2*)(smem + QC_OFF);      // compact (qg, kv) pairs

    // pass 1: (q,k,v,g) -> compact (q*sigmoid(g), kv); accumulate kv sum
    float psum = 0.0f;
#pragma unroll 4
    for (int r = rg * 16; r < rg * 16 + 16; r++) {
        float4 c4 = ((const float4*)C)[r * 32 + dl];
        float qv = c4.x + bias.x;
        float kv = (c4.y + bias.y) * (c4.z + bias.z);
        float gt = c4.w + bias.w;
        float gs = 1.0f / (1.0f + __expf(-gt));
        Qc[r * 32 + dl] = make_float2(qv * gs, kv);
        psum += kv;
    }
    float* red  = (float*)(smem + RED_OFF);      // 256 floats
    float* red2 = (float*)(smem + RED2_OFF);     // 32 floats
    red[rg * 32 + dl] = psum;
    __syncthreads();

    // chained scan across chunks (bm within same batch of 32)
    if (tid < 32) {
        const int d = tid;
        float ex = 0.0f;
#pragma unroll
        for (int j = 0; j < 8; j++) {
            float t = red[j * 32 + d];
            red[j * 32 + d] = ex;        // exclusive group offset
            ex += t;
        }
        float P = 0.0f;
        if ((bm & 31) != 0) {
            volatile unsigned int* fl = &g_flag[(bm - 1) * NBN + bn];
            while (*fl == 0u) __nanosleep(40);
            __threadfence();
            P = g_pref[(size_t)(bm - 1) * DIM + bn * 32 + d];
        }
        red2[d] = P;
        g_pref[(size_t)bm * DIM + bn * 32 + d] = P + ex;
        __threadfence();
    }
    __syncthreads();
    if (tid == 0) {
        __threadfence();
        atomicExch(&g_flag[bm * NBN + bn], 1u);
    }

    // pass 2: running cumsum + output (reads back only own-thread pairs)
    float racc = red2[dl] + red[rg * 32 + dl];
    const size_t m0 = (size_t)bm * BM;
#pragma unroll 4
    for (int r = rg * 16; r < rg * 16 + 16; r++) {
        float2 p2 = Qc[r * 32 + dl];
        racc += p2.y;
        out[(m0 + r) * DIM + dg] = p2.x * racc;
    }
}

// ---------------------------------------------------------------- launch
extern "C" void kernel_launch(void* const* d_in, const int* in_sizes, int n_in,
                              void* d_out, int out_size)
{
    const float* x    = (const float*)d_in[0];
    const float* Wqkv = (const float*)d_in[1];
    const float* bqkv = (const float*)d_in[2];
    const float* Wg   = (const float*)d_in[3];
    const float* bg   = (const float*)d_in[4];
    float* out        = (float*)d_out;

    setup_kernel<<<XB + NN + (NBM * NBN) / 256, 256>>>(x, Wqkv, bqkv, Wg, bg);

    cudaFuncSetAttribute(gemm_fused_kernel,
                         cudaFuncAttributeMaxDynamicSharedMemorySize, GEMM_SMEM);
    dim3 ggrid(NBN, NBM);                  // (32, 128), bn minor -> bm-1 earlier
    gemm_fused_kernel<<<ggrid, 256, GEMM_SMEM>>>(out);
}

// round 17
// speedup vs baseline: 1.0512x; 1.0512x over previous
#include <cuda_runtime.h>
#include <cuda_fp16.h>
#include <cstdint>

// ---------------------------------------------------------------- shapes
#define BATCH 4
#define SEQ   4096
#define DIM   1024
#define MM    (BATCH * SEQ)   // 16384
#define KK    DIM             // 1024
#define NN    (4 * DIM)       // 4096 : interleaved [q k v g] per dim

// GEMM tiling
#define BM 128
#define BN 128
#define BK 64
#define KITERS (KK / BK)      // 16
#define NBM (MM / BM)         // 128  (= 4 batches x 32 chunks)
#define NBN (NN / BN)         // 32

// ---------------------------------------------------------------- scratch
static __device__ __half g_Ah[(size_t)MM * KK];
static __device__ __half g_Wh[(size_t)NN * KK];     // column-permuted: e' = 4d+j
static __device__ float  g_ball[NN];                 // permuted bias
static __device__ float          g_pref[(size_t)NBM * DIM];  // inclusive chunk prefixes
static __device__ unsigned int   g_flag[NBM * NBN];          // publication flags

// ---------------------------------------------------------------- helpers
__device__ __forceinline__ uint32_t smem_u32(const void* p) {
    uint32_t a;
    asm("{ .reg .u64 t; cvta.to.shared.u64 t, %1; cvt.u32.u64 %0, t; }" : "=r"(a) : "l"(p));
    return a;
}

__device__ __forceinline__ void cp_async16(uint32_t smem_addr, const void* gptr) {
    asm volatile("cp.async.cg.shared.global [%0], [%1], 16;"
                 :: "r"(smem_addr), "l"(gptr) : "memory");
}
#define CP_COMMIT() asm volatile("cp.async.commit_group;" ::: "memory")
#define CP_WAIT1()  asm volatile("cp.async.wait_group 1;" ::: "memory")
#define CP_WAIT0()  asm volatile("cp.async.wait_group 0;" ::: "memory")

__device__ __forceinline__ void ldm_x4(uint32_t* r, uint32_t addr) {
    asm volatile("ldmatrix.sync.aligned.m8n8.x4.shared.b16 {%0,%1,%2,%3}, [%4];"
                 : "=r"(r[0]), "=r"(r[1]), "=r"(r[2]), "=r"(r[3]) : "r"(addr));
}

__device__ __forceinline__ void mma16816(float* c, const uint32_t* a, const uint32_t* b) {
    asm volatile(
        "mma.sync.aligned.m16n8k16.row.col.f32.f16.f16.f32 "
        "{%0,%1,%2,%3}, {%4,%5,%6,%7}, {%8,%9}, {%0,%1,%2,%3};"
        : "+f"(c[0]), "+f"(c[1]), "+f"(c[2]), "+f"(c[3])
        : "r"(a[0]), "r"(a[1]), "r"(a[2]), "r"(a[3]), "r"(b[0]), "r"(b[1]));
}

// ---------------------------------------------------------------- merged setup
#define XB (MM * KK / 4 / 256)
__global__ __launch_bounds__(256)
void setup_kernel(const float* __restrict__ x,
                  const float* __restrict__ Wqkv, const float* __restrict__ bqkv,
                  const float* __restrict__ Wg,   const float* __restrict__ bg)
{
    int blk = blockIdx.x;
    int t   = threadIdx.x;
    if (blk < XB) {
        size_t i = (size_t)blk * 256 + t;
        float4 v = ((const float4*)x)[i];
        size_t o = i * 4;
        g_Ah[o + 0] = __float2half_rn(v.x);
        g_Ah[o + 1] = __float2half_rn(v.y);
        g_Ah[o + 2] = __float2half_rn(v.z);
        g_Ah[o + 3] = __float2half_rn(v.w);
    } else if (blk < XB + NN) {
        int ep = blk - XB;
        int d  = ep >> 2;
        int j  = ep & 3;
        const float* src = (j < 3) ? (Wqkv + (size_t)(j * DIM + d) * KK)
                                   : (Wg + (size_t)d * KK);
        float4 v = ((const float4*)src)[t];
        size_t o = (size_t)ep * KK + t * 4;
        g_Wh[o + 0] = __float2half_rn(v.x);
        g_Wh[o + 1] = __float2half_rn(v.y);
        g_Wh[o + 2] = __float2half_rn(v.z);
        g_Wh[o + 3] = __float2half_rn(v.w);
        if (t == 0)
            g_ball[ep] = (j < 3) ? bqkv[j * DIM + d] : bg[d];
    } else {
        int i = (blk - XB - NN) * 256 + t;
        g_flag[i] = 0u;
    }
}

// ---------------------------------------------------------------- GEMM + fused scan
// SMEM mainloop: stage = A(128x64, pad 72) | B(128x64) = 36864 B; 3 stages = 110592.
// Epilogue overlay: C tile [0,64K); compact (qg,kv) pairs @65536 (32KB);
//                   red @98304 (1KB); red2 @99328.
#define TPAD 72
#define TROW (TPAD * 2)                  // 144 B row stride
#define TILE_B (128 * TROW)              // 18432
#define OFF_A 0
#define OFF_B (TILE_B)
#define STAGE_B (2 * TILE_B)             // 36864
#define NSTAGE 3
#define QC_OFF  65536
#define RED_OFF 98304
#define RED2_OFF 99328
#define GEMM_SMEM (NSTAGE * STAGE_B)     // 110592

// Full-tile load (prologue only).
__device__ __forceinline__ void load_tile(uint32_t s_dst, const __half* g_src,
                                          int k0, int tid)
{
#pragma unroll
    for (int it = 0; it < 4; it++) {
        int c   = tid + it * 256;        // [0,1024)
        int row = c >> 3;
        int kc  = c & 7;
        cp_async16(s_dst + (uint32_t)(row * TROW + kc * 16),
                   (const char*)(g_src + (size_t)row * KK + k0) + kc * 16);
    }
}

__global__ __launch_bounds__(256, 2)
void gemm_fused_kernel(float* __restrict__ out)
{
    extern __shared__ char smem[];
    const uint32_t sb = smem_u32(smem);
    const int tid  = threadIdx.x;
    const int wid  = tid >> 5;
    const int lane = tid & 31;
    const int bm   = blockIdx.y;
    const int bn   = blockIdx.x;
    const int wM   = wid & 3;            // 0..3  (M warp, 32 rows)
    const int wN   = wid >> 2;           // 0..1  (N warp, 64 cols)

    const __half* Ah = g_Ah + (size_t)bm * BM * KK;
    const __half* Bh = g_Wh + (size_t)bn * BN * KK;

    float acc[2][8][4];                  // mi x ni x frag (64 regs)
#pragma unroll
    for (int i = 0; i < 2; i++)
#pragma unroll
        for (int j = 0; j < 8; j++)
#pragma unroll
            for (int r = 0; r < 4; r++) acc[i][j][r] = 0.0f;

    // ldmatrix lane addressing (verified R4-R16):
    const int aRow = wM * 32 + (lane & 15);
    const int aCol = (lane >> 4) * 8;
    const int bRowN = wN * 64 + ((lane >> 4) * 8) + (lane & 7);
    const int bColK = ((lane >> 3) & 1) * 8;
    const uint32_t aOff = (uint32_t)(aRow * TROW + aCol * 2);
    const uint32_t bOff = (uint32_t)(bRowN * TROW + bColK * 2);

    // per-thread cp.async quarter addressing
    const int ldRow = tid >> 3;          // row base within quarter 0 [0,32)
    const int ldKc  = (tid & 7) * 16;    // byte offset within 128B row span

    // ---- prologue: stages 0,1
    load_tile(sb + 0 * STAGE_B + OFF_A, Ah, 0, tid);
    load_tile(sb + 0 * STAGE_B + OFF_B, Bh, 0, tid);
    CP_COMMIT();
    load_tile(sb + 1 * STAGE_B + OFF_A, Ah, BK, tid);
    load_tile(sb + 1 * STAGE_B + OFF_B, Bh, BK, tid);
    CP_COMMIT();

    int slot = 0, nslot = 2;
    for (int i = 0; i < KITERS; i++) {
        if (i < KITERS - 1) { CP_WAIT1(); } else { CP_WAIT0(); }
        __syncthreads();                 // stage i resident; compute(i-1) done

        const bool pf = (i + 2 < KITERS);
        const uint32_t nb = sb + (uint32_t)nslot * STAGE_B;
        const int k0 = (i + 2) * BK;

        const uint32_t aBase = sb + (uint32_t)slot * STAGE_B + OFF_A + aOff;
        const uint32_t bBase = sb + (uint32_t)slot * STAGE_B + OFF_B + bOff;

        // ---- software-pipelined window; prefetch quarter at each slice top
        uint32_t afq[2][2][4];           // [slice parity][mi][4]
        uint32_t bq[2][4];               // rotating B pair buffer
        ldm_x4(afq[0][0], aBase);
        ldm_x4(afq[0][1], aBase + 16 * TROW);
        ldm_x4(bq[0], bBase);
#pragma unroll
        for (int ks = 0; ks < 4; ks++) {
            const int kc = ks & 1;
            // one prefetch quarter per slice: 1 A-chunk + 1 B-chunk per thread
            if (pf) {
                int row = ldRow + ks * 32;
                uint32_t so = (uint32_t)(row * TROW + ldKc);
                const char* gp = (const char*)(Ah + (size_t)row * KK + k0) + ldKc;
                cp_async16(nb + OFF_A + so, gp);
                const char* gq = (const char*)(Bh + (size_t)row * KK + k0) + ldKc;
                cp_async16(nb + OFF_B + so, gq);
            }
#pragma unroll
            for (int nh = 0; nh < 4; nh++) {
                const int p = nh & 1;
                if (nh < 3)
                    ldm_x4(bq[p ^ 1], bBase + (uint32_t)((nh + 1) * 16 * TROW + ks * 32));
                else if (ks < 3)
                    ldm_x4(bq[p ^ 1], bBase + (uint32_t)((ks + 1) * 32));
                if (ks < 3) {
                    if (nh == 1) ldm_x4(afq[kc ^ 1][0], aBase + (uint32_t)((ks + 1) * 32));
                    if (nh == 2) ldm_x4(afq[kc ^ 1][1], aBase + (uint32_t)(16 * TROW + (ks + 1) * 32));
                }
                mma16816(acc[0][2 * nh],     afq[kc][0], &bq[p][0]);
                mma16816(acc[0][2 * nh + 1], afq[kc][0], &bq[p][2]);
                mma16816(acc[1][2 * nh],     afq[kc][1], &bq[p][0]);
                mma16816(acc[1][2 * nh + 1], afq[kc][1], &bq[p][2]);
            }
        }
        if (pf) CP_COMMIT();
        slot  = (slot == NSTAGE - 1) ? 0 : slot + 1;
        nslot = (nslot == NSTAGE - 1) ? 0 : nslot + 1;
    }

    // ---- fused epilogue with decoupled chained scan --------------------
    __syncthreads();                     // all ldmatrix reads done
    float* C = (float*)smem;             // 128 x 128 f32
    const int g   = lane >> 2;
    const int tig = lane & 3;
#pragma unroll
    for (int mi = 0; mi < 2; mi++) {
#pragma unroll
        for (int ni = 0; ni < 8; ni++) {
            int col  = wN * 64 + ni * 8 + tig * 2;
            int row0 = wM * 32 + mi * 16 + g;
            C[row0 * 128 + col]           = acc[mi][ni][0];
            C[row0 * 128 + col + 1]       = acc[mi][ni][1];
            C[(row0 + 8) * 128 + col]     = acc[mi][ni][2];
            C[(row0 + 8) * 128 + col + 1] = acc[mi][ni][3];
        }
    }
    __syncthreads();

    const int dl = tid & 31;             // local dim 0..31
    const int rg = tid >> 5;             // row group 0..7 (16 rows each)
    const int dg = bn * 32 + dl;         // global dim
    float4 bias = ((const float4*)g_ball)[dg];
    float2* Qc  = (float2*)(smem + QC_OFF);      // compact (qg, kv) pairs

    // pass 1: (q,k,v,g) -> compact (q*sigmoid(g), kv); accumulate kv sum
    float psum = 0.0f;
#pragma unroll 4
    for (int r = rg * 16; r < rg * 16 + 16; r++) {
        float4 c4 = ((const float4*)C)[r * 32 + dl];
        float qv = c4.x + bias.x;
        float kv = (c4.y + bias.y) * (c4.z + bias.z);
        float gt = c4.w + bias.w;
        float gs = 1.0f / (1.0f + __expf(-gt));
        Qc[r * 32 + dl] = make_float2(qv * gs, kv);
        psum += kv;
    }
    float* red  = (float*)(smem + RED_OFF);      // 256 floats
    float* red2 = (float*)(smem + RED2_OFF);     // 32 floats
    red[rg * 32 + dl] = psum;
    __syncthreads();

    // chained scan across chunks (bm within same batch of 32)
    if (tid < 32) {
        const int d = tid;
        float ex = 0.0f;
#pragma unroll
        for (int j = 0; j < 8; j++) {
            float t = red[j * 32 + d];
            red[j * 32 + d] = ex;        // exclusive group offset
            ex += t;
        }
        float P = 0.0f;
        if ((bm & 31) != 0) {
            volatile unsigned int* fl = &g_flag[(bm - 1) * NBN + bn];
            while (*fl == 0u) __nanosleep(40);
            __threadfence();
            P = g_pref[(size_t)(bm - 1) * DIM + bn * 32 + d];
        }
        red2[d] = P;
        g_pref[(size_t)bm * DIM + bn * 32 + d] = P + ex;
        __threadfence();
    }
    __syncthreads();
    if (tid == 0) {
        __threadfence();
        atomicExch(&g_flag[bm * NBN + bn], 1u);
    }

    // pass 2: running cumsum + output (reads back only own-thread pairs)
    float racc = red2[dl] + red[rg * 32 + dl];
    const size_t m0 = (size_t)bm * BM;
#pragma unroll 4
    for (int r = rg * 16; r < rg * 16 + 16; r++) {
        float2 p2 = Qc[r * 32 + dl];
        racc += p2.y;
        out[(m0 + r) * DIM + dg] = p2.x * racc;
    }
}

// ---------------------------------------------------------------- launch
extern "C" void kernel_launch(void* const* d_in, const int* in_sizes, int n_in,
                              void* d_out, int out_size)
{
    const float* x    = (const float*)d_in[0];
    const float* Wqkv = (const float*)d_in[1];
    const float* bqkv = (const float*)d_in[2];
    const float* Wg   = (const float*)d_in[3];
    const float* bg   = (const float*)d_in[4];
    float* out        = (float*)d_out;

    setup_kernel<<<XB + NN + (NBM * NBN) / 256, 256>>>(x, Wqkv, bqkv, Wg, bg);

    cudaFuncSetAttribute(gemm_fused_kernel,
                         cudaFuncAttributeMaxDynamicSharedMemorySize, GEMM_SMEM);
    dim3 ggrid(NBN, NBM);                  // (32, 128), bn minor -> bm-1 earlier
    gemm_fused_kernel<<<ggrid, 256, GEMM_SMEM>>>(out);
}